// round 3
// baseline (speedup 1.0000x reference)
#include <cuda_runtime.h>
#include <cstdint>
#include <cstddef>

#define WIDTH  2048
#define DEPTH  8
#define DP1    9
#define TMOD   242          // 30*DEPTH + 2
#define WD     16384        // WIDTH*DEPTH
#define KBLK   64           // k-blocks (blockIdx.x), 256 k each
#define NSPLIT 16           // i-splits (blockIdx.y), 128 i each
#define CHUNK  128
#define SUBI   32           // i rows per smem subtile
#define NSUB   4            // CHUNK / SUBI
#define STRIDE 264          // smem row stride in floats (256 + 8 pad)

// d_out layout (float32, reference return order)
#define OFF_OUT   0ULL
#define OFF_STATE 1ULL
#define OFF_SA    18433ULL
#define OFF_SG    4478977ULL
#define OFF_OG    4495361ULL
#define OFF_GRAD  8955905ULL
#define OFF_OWG   42510337ULL

// scratch (allocation-free)
__device__ float g_hpart[NSPLIT][WD];     // hidden partials (1 MB)
__device__ float g_cpart[KBLK][WD];       // contrib partials (4 MB)
__device__ float g_m[WD];
__device__ float g_aprev[WD];
__device__ float g_out_acc;

__device__ __forceinline__ int posmod(int v, int m) {
    int r = v % m;
    return r < 0 ? r + m : r;
}

// ---------------------------------------------------------------------------
// K1: single DRAM pass over W; two smem phases per 32x256 tile.
//   hidden[k]    = sum_i W[i*WD+k] * state[i, k&7]
//   contrib[i,d] = sum_j W[i*WD+j*8+d] * sg[j*8+d]   (slot d; d=0 zeroed)
// ---------------------------------------------------------------------------
__global__ void k_fusedW(const float* __restrict__ W,
                         const float* __restrict__ state_in,
                         const float* __restrict__ sgrad) {
    __shared__ float tile[SUBI * STRIDE];   // 33 KB
    __shared__ float ss[CHUNK * 8];         // 4 KB state chunk
    __shared__ float ssg[256];              // 1 KB sg slice for this k-block

    const int tid = threadIdx.x;
    const int k0  = blockIdx.x * 256;
    const int k   = k0 + tid;
    const int i0  = blockIdx.y * CHUNK;
    const int d   = tid & 7;

    if (blockIdx.x == 0 && blockIdx.y == 0 && tid == 0) g_out_acc = 0.f;

    ssg[tid] = (d == 0) ? 0.f : sgrad[k];
    for (int idx = tid; idx < CHUNK * 8; idx += 256) {
        int i = idx >> 3, dd = idx & 7;
        ss[idx] = state_in[(size_t)(i0 + i) * DP1 + dd];
    }

    const int il = tid >> 3;   // contrib-phase row 0..31
    float hacc = 0.f;

    for (int sub = 0; sub < NSUB; ++sub) {
        const int ibase = sub * SUBI;
        __syncthreads();   // protect tile reuse (and first-iter ss/ssg)
        // load 32x256 tile (2048 float4, 8 per thread)
        for (int f = tid; f < SUBI * 64; f += 256) {
            int r = f >> 6, c4 = f & 63;
            float4 v = *reinterpret_cast<const float4*>(
                W + (size_t)(i0 + ibase + r) * WD + k0 + c4 * 4);
            *reinterpret_cast<float4*>(&tile[r * STRIDE + c4 * 4]) = v;
        }
        __syncthreads();

        // phase 1: hidden column-reduce (thread = column k)
#pragma unroll 8
        for (int i = 0; i < SUBI; ++i)
            hacc = fmaf(tile[i * STRIDE + tid], ss[(ibase + i) * 8 + d], hacc);

        // phase 2: contrib row-reduce (thread = (il, d)); conflict-free
        float cacc = 0.f;
#pragma unroll 8
        for (int j = 0; j < 32; ++j)
            cacc = fmaf(tile[il * STRIDE + j * 8 + d], ssg[j * 8 + d], cacc);
        g_cpart[blockIdx.x][(size_t)(i0 + ibase + il) * 8 + d] = cacc;
    }
    g_hpart[blockIdx.y][k] = hacc;
}

// ---------------------------------------------------------------------------
// K2: finalize — state/owg, contrib sum, output dot, AND the full sg logic.
// Index identity: thread k -> (w = k>>3, a = k&7) matches sg layout exactly.
// Proof used: tia(a) = time + 2a - 14 (mod 242). tia==time only for a=7;
// (tia+1)!=time and (tia-1)!=time for all a. So all sa/og reads at a<7 hit the
// ORIGINAL arrays; at a=7 the only aliased value is this thread's own state.
// ---------------------------------------------------------------------------
__global__ void k_finalize(float* __restrict__ out,
                           const float* __restrict__ x,
                           const float* __restrict__ ow,
                           const float* __restrict__ sa_in,
                           const float* __restrict__ og_in,
                           const int* __restrict__ time_p) {
    const int k = blockIdx.x * blockDim.x + threadIdx.x;   // 0..WD-1
    const int w = k >> 3, a = k & 7;

    float h = 0.f;
#pragma unroll
    for (int c = 0; c < NSPLIT; ++c) h += g_hpart[c][k];
    float s = fmaxf(h, 0.f);

    float cb = 0.f;
#pragma unroll 8
    for (int b = 0; b < KBLK; ++b) cb += g_cpart[b][k];
    // sg needs contrib at slot d=a+1 -> neighbor lane (same w group)
    float cbn = __shfl_down_sync(0xffffffffu, cb, 1);

    size_t o = (size_t)w * DP1 + a + 1;
    out[OFF_STATE + o] = s;
    out[OFF_OWG + o]   = s;
    float v = ow[o] * s;
    if (a == 0) {
        float xv = x[w];
        out[OFF_STATE + (size_t)w * DP1] = xv;
        out[OFF_OWG   + (size_t)w * DP1] = xv;
        v = fmaf(ow[(size_t)w * DP1], xv, v);
    }

    // ---- sg / m / act_prev ----
    const int time = *time_p;
    const int tia = posmod(time - 2 * DEPTH + 2 * (a + 1), TMOD);
    float sgv, rg, aprev;
    if (a < DEPTH - 1) {
        int t1 = (tia + 1) % TMOD;
        float rmv = sa_in[((size_t)w * DP1 + a + 2) * TMOD + t1];
        sgv = fmaf(rmv > 0.f ? 1.f : 0.f, cbn,
                   og_in[((size_t)w * DP1 + a + 1) * TMOD + tia]);
        rg = (sa_in[((size_t)w * DP1 + a + 1) * TMOD + tia] > 0.f) ? 1.f : 0.f;
        aprev = sa_in[((size_t)w * DP1 + a) * TMOD + posmod(tia - 1, TMOD)];
    } else {
        sgv = ow[(size_t)w * DP1 + DEPTH];
        rg = (s > 0.f) ? 1.f : 0.f;                       // state[w,8] == own s
        aprev = sa_in[((size_t)w * DP1 + DEPTH - 1) * TMOD + posmod(time - 1, TMOD)];
    }
    out[OFF_SG + k] = sgv;
    g_m[k] = sgv * rg;
    g_aprev[k] = aprev;

    // ---- output scalar: block reduce + one atomic ----
    __shared__ float red[8];
#pragma unroll
    for (int off = 16; off; off >>= 1)
        v += __shfl_down_sync(0xffffffffu, v, off);
    if ((threadIdx.x & 31) == 0) red[threadIdx.x >> 5] = v;
    __syncthreads();
    if (threadIdx.x == 0) {
        float t = 0.f;
#pragma unroll
        for (int i = 0; i < 8; ++i) t += red[i];
        atomicAdd(&g_out_acc, t);
    }
}

// ---------------------------------------------------------------------------
// K3: sa / og copies with time-slice replaced; float4 input loads.
// ---------------------------------------------------------------------------
__global__ void k_saog(float* __restrict__ out,
                       const float* __restrict__ sa_in,
                       const float* __restrict__ og_in,
                       const float* __restrict__ ow,
                       const int* __restrict__ time_p) {
    const int time = *time_p;
    const int nq = (WIDTH * DP1 * TMOD) / 4;
    int q = blockIdx.x * blockDim.x + threadIdx.x;
    if (q >= nq) return;
    int idx = q * 4;
    float4 sav = reinterpret_cast<const float4*>(sa_in)[q];
    float4 ogv = reinterpret_cast<const float4*>(og_in)[q];
    float sv[4] = {sav.x, sav.y, sav.z, sav.w};
    float ov[4] = {ogv.x, ogv.y, ogv.z, ogv.w};
    int t = idx % TMOD;
    int wc = idx / TMOD;
#pragma unroll
    for (int e = 0; e < 4; ++e) {
        int tt = t + e, wcc = wc;
        if (tt >= TMOD) { tt -= TMOD; ++wcc; }
        if (tt == time) {
            sv[e] = out[OFF_STATE + wcc];
            ov[e] = ow[wcc];
        }
        out[OFF_SA + idx + e] = sv[e];
        out[OFF_OG + idx + e] = ov[e];
    }
}

// ---------------------------------------------------------------------------
// K4: gradients[i,j,a] = act_prev[i,a] * m[j,a]; per-thread ap is constant.
// Also publishes the output scalar.
// ---------------------------------------------------------------------------
__global__ void k_grad(float* __restrict__ out) {
    const int i = blockIdx.x;
    if (i == 0 && threadIdx.x == 0) out[OFF_OUT] = g_out_acc;
    const float apv = g_aprev[(size_t)i * 8 + (threadIdx.x & 7)];
    float* dst = out + OFF_GRAD + (size_t)i * WD;
#pragma unroll 8
    for (int k = threadIdx.x; k < WD; k += 256)
        dst[k] = apv * g_m[k];
}

// ---------------------------------------------------------------------------
extern "C" void kernel_launch(void* const* d_in, const int* in_sizes, int n_in,
                              void* d_out, int out_size) {
    const float* x    = (const float*)d_in[0];
    const float* W    = (const float*)d_in[1];
    const float* ow   = (const float*)d_in[2];
    const float* st   = (const float*)d_in[3];
    const float* sa   = (const float*)d_in[4];
    const float* sgr  = (const float*)d_in[5];
    const float* og   = (const float*)d_in[6];
    const int*   tim  = (const int*)d_in[7];
    float* out = (float*)d_out;

    k_fusedW<<<dim3(KBLK, NSPLIT), 256>>>(W, st, sgr);
    k_finalize<<<WD / 256, 256>>>(out, x, ow, sa, og, tim);
    k_saog<<<(WIDTH * DP1 * TMOD / 4 + 255) / 256, 256>>>(out, sa, og, ow, tim);
    k_grad<<<WIDTH, 256>>>(out);
}

// round 4
// speedup vs baseline: 1.3376x; 1.3376x over previous
#include <cuda_runtime.h>
#include <cstdint>
#include <cstddef>

#define WIDTH  2048
#define DEPTH  8
#define DP1    9
#define TMOD   242          // 30*DEPTH + 2
#define WD     16384        // WIDTH*DEPTH
#define NSPLIT 16           // i-splits (blockIdx.y)
#define KBLK   64           // k-blocks  (blockIdx.x)
#define CHUNK  128          // WIDTH / NSPLIT

// d_out layout (float32, reference return order)
#define OFF_OUT   0ULL
#define OFF_STATE 1ULL
#define OFF_SA    18433ULL
#define OFF_SG    4478977ULL
#define OFF_OG    4495361ULL
#define OFF_GRAD  8955905ULL
#define OFF_OWG   42510337ULL

#define N_SAOG    (WIDTH * DP1 * TMOD)     // 4460544
#define NQ_SAOG   1115135                  // quads idx = 3+4q, q in [0, NQ)
#define NQ_GROW   4095                     // per-row quads k = 3+4q

// scratch (allocation-free)
__device__ float g_hpart[NSPLIT][WD];     // hidden partials (1 MB)
__device__ float g_cpart[KBLK][WD];       // contrib partials (4 MB)
__device__ float g_m[WD];
__device__ float g_aprev[WD];
__device__ float g_out_acc;

__device__ __forceinline__ int posmod(int v, int m) {
    int r = v % m;
    return r < 0 ? r + m : r;
}

// ---------------------------------------------------------------------------
// K1: single pass over W, both reductions (round-2 shuffle scheme — measured
// faster than the two-phase smem-tile variant).
//   hidden[k]    = sum_i W[i*WD+k] * state[i, k&7]
//   contrib[i,d] = sum_j W[i*WD+j*8+d] * sg[j*8+d]   (slot d; d=0 zeroed)
// ---------------------------------------------------------------------------
__global__ void k_fusedW(const float* __restrict__ W,
                         const float* __restrict__ state_in,
                         const float* __restrict__ sgrad) {
    __shared__ float ss[CHUNK * 8];          // state chunk (4 KB)
    __shared__ float csm[8 * CHUNK * 8];     // per-warp contrib partials (32 KB)

    const int tid = threadIdx.x;
    const int k   = blockIdx.x * 256 + tid;
    const int i0  = blockIdx.y * CHUNK;
    const int wid = tid >> 5, lane = tid & 31;
    const int d   = k & 7;                   // == lane & 7

    if (blockIdx.x == 0 && blockIdx.y == 0 && tid == 0) g_out_acc = 0.f;

    for (int idx = tid; idx < CHUNK * 8; idx += 256) {
        int i = idx >> 3, dd = idx & 7;
        ss[idx] = state_in[(size_t)(i0 + i) * DP1 + dd];
    }
    __syncthreads();

    const float sgf = (d == 0) ? 0.f : sgrad[k];
    const float* Wp = W + (size_t)i0 * WD + k;

    float acc = 0.f;
#pragma unroll 8
    for (int i = 0; i < CHUNK; ++i) {
        float w = Wp[(size_t)i * WD];
        acc = fmaf(w, ss[i * 8 + d], acc);
        float p = w * sgf;
        p += __shfl_xor_sync(0xffffffffu, p, 8);
        p += __shfl_xor_sync(0xffffffffu, p, 16);
        if (lane < 8) csm[(wid * CHUNK + i) * 8 + lane] = p;
    }
    g_hpart[blockIdx.y][k] = acc;

    __syncthreads();
    for (int idx = tid; idx < CHUNK * 8; idx += 256) {
        float s = 0.f;
#pragma unroll
        for (int w = 0; w < 8; ++w) s += csm[w * CHUNK * 8 + idx];
        g_cpart[blockIdx.x][(size_t)i0 * 8 + idx] = s;
    }
}

// ---------------------------------------------------------------------------
// K2: finalize — state/owg, contrib sum, output dot, full sg logic.
// tia(a) = time + 2a - 14 (mod 242); tia==time only at a=7, and (tia±1)!=time
// for all a, so all sa/og reads at a<7 hit the ORIGINAL arrays; at a=7 the
// only aliased read is this thread's own fresh state value.
// ---------------------------------------------------------------------------
__global__ void k_finalize(float* __restrict__ out,
                           const float* __restrict__ x,
                           const float* __restrict__ ow,
                           const float* __restrict__ sa_in,
                           const float* __restrict__ og_in,
                           const int* __restrict__ time_p) {
    const int k = blockIdx.x * blockDim.x + threadIdx.x;   // 0..WD-1
    const int w = k >> 3, a = k & 7;

    float h = 0.f;
#pragma unroll
    for (int c = 0; c < NSPLIT; ++c) h += g_hpart[c][k];
    float s = fmaxf(h, 0.f);

    float cb = 0.f;
#pragma unroll 8
    for (int b = 0; b < KBLK; ++b) cb += g_cpart[b][k];
    float cbn = __shfl_down_sync(0xffffffffu, cb, 1);   // slot d = a+1

    size_t o = (size_t)w * DP1 + a + 1;
    out[OFF_STATE + o] = s;
    out[OFF_OWG + o]   = s;
    float v = ow[o] * s;
    if (a == 0) {
        float xv = x[w];
        out[OFF_STATE + (size_t)w * DP1] = xv;
        out[OFF_OWG   + (size_t)w * DP1] = xv;
        v = fmaf(ow[(size_t)w * DP1], xv, v);
    }

    const int time = *time_p;
    const int tia = posmod(time - 2 * DEPTH + 2 * (a + 1), TMOD);
    float sgv, rg, aprev;
    if (a < DEPTH - 1) {
        int t1 = (tia + 1) % TMOD;
        float rmv = sa_in[((size_t)w * DP1 + a + 2) * TMOD + t1];
        sgv = fmaf(rmv > 0.f ? 1.f : 0.f, cbn,
                   og_in[((size_t)w * DP1 + a + 1) * TMOD + tia]);
        rg = (sa_in[((size_t)w * DP1 + a + 1) * TMOD + tia] > 0.f) ? 1.f : 0.f;
        aprev = sa_in[((size_t)w * DP1 + a) * TMOD + posmod(tia - 1, TMOD)];
    } else {
        sgv = ow[(size_t)w * DP1 + DEPTH];
        rg = (s > 0.f) ? 1.f : 0.f;
        aprev = sa_in[((size_t)w * DP1 + DEPTH - 1) * TMOD + posmod(time - 1, TMOD)];
    }
    out[OFF_SG + k] = sgv;
    g_m[k] = sgv * rg;
    g_aprev[k] = aprev;

    __shared__ float red[8];
#pragma unroll
    for (int off = 16; off; off >>= 1)
        v += __shfl_down_sync(0xffffffffu, v, off);
    if ((threadIdx.x & 31) == 0) red[threadIdx.x >> 5] = v;
    __syncthreads();
    if (threadIdx.x == 0) {
        float t = 0.f;
#pragma unroll
        for (int i = 0; i < 8; ++i) t += red[i];
        atomicAdd(&g_out_acc, t);
    }
}

// ---------------------------------------------------------------------------
// K3: sa / og copies, SECTOR-ALIGNED stores.
// Quad q handles idx = 3+4q so out-addresses (OFF_SA/OFF_OG ≡ 1 mod 4) are
// 16B-aligned. Reads use two overlapping aligned float4s (coalesced).
// ---------------------------------------------------------------------------
__global__ void k_saog(float* __restrict__ out,
                       const float* __restrict__ sa_in,
                       const float* __restrict__ og_in,
                       const float* __restrict__ ow,
                       const int* __restrict__ time_p) {
    const int time = *time_p;
    const int q = blockIdx.x * blockDim.x + threadIdx.x;
    if (q >= NQ_SAOG) return;
    const int idx = 3 + 4 * q;

    const float4* sa4 = reinterpret_cast<const float4*>(sa_in);
    const float4* og4 = reinterpret_cast<const float4*>(og_in);
    float4 sA = sa4[q], sB = sa4[q + 1];
    float4 oA = og4[q], oB = og4[q + 1];
    float sv[4] = {sA.w, sB.x, sB.y, sB.z};
    float ov[4] = {oA.w, oB.x, oB.y, oB.z};

    int t  = idx % TMOD;
    int wc = idx / TMOD;
#pragma unroll
    for (int e = 0; e < 4; ++e) {
        int tt = t + e, wcc = wc;
        if (tt >= TMOD) { tt -= TMOD; ++wcc; }
        if (tt == time) {
            sv[e] = out[OFF_STATE + wcc];
            ov[e] = ow[wcc];
        }
    }
    *reinterpret_cast<float4*>(&out[OFF_SA + idx]) = make_float4(sv[0], sv[1], sv[2], sv[3]);
    *reinterpret_cast<float4*>(&out[OFF_OG + idx]) = make_float4(ov[0], ov[1], ov[2], ov[3]);

    if (q == 0) {
        // head: idx 0,1,2  (wc = 0, t = 0,1,2)
#pragma unroll
        for (int e = 0; e < 3; ++e) {
            float svh = (e == time) ? out[OFF_STATE] : sa_in[e];
            float ovh = (e == time) ? ow[0] : og_in[e];
            out[OFF_SA + e] = svh;
            out[OFF_OG + e] = ovh;
        }
    }
    if (q == NQ_SAOG - 1) {
        // tail: idx N-1 (t = 241, wc = WIDTH*DP1-1); 241==time impossible only
        // if time<241 — handle generically
        const int it = N_SAOG - 1;
        int tt = it % TMOD, wcc = it / TMOD;
        out[OFF_SA + it] = (tt == time) ? out[OFF_STATE + wcc] : sa_in[it];
        out[OFF_OG + it] = (tt == time) ? ow[wcc] : og_in[it];
    }
}

// ---------------------------------------------------------------------------
// K4: gradients[i,j,a] = act_prev[i,a] * m[j,a], SECTOR-ALIGNED stores.
// Row base ≡ 1 mod 4 -> head {k=0,1,2}, aligned quads k=3+4q, tail {k=16383}.
// Quad d-pattern: q even -> (3,4,5,6); q odd -> (7,0,1,2). q parity == tid&1.
// ---------------------------------------------------------------------------
__global__ void k_grad(float* __restrict__ out) {
    const int i = blockIdx.x;
    const int tid = threadIdx.x;
    if (i == 0 && tid == 0) out[OFF_OUT] = g_out_acc;

    const float* ap = g_aprev + (size_t)i * 8;
    float4 apv;
    if ((tid & 1) == 0)
        apv = make_float4(__ldg(ap + 3), __ldg(ap + 4), __ldg(ap + 5), __ldg(ap + 6));
    else
        apv = make_float4(__ldg(ap + 7), __ldg(ap + 0), __ldg(ap + 1), __ldg(ap + 2));

    float* dst = out + OFF_GRAD + (size_t)i * WD;
    const float4* m4 = reinterpret_cast<const float4*>(g_m);

    for (int q = tid; q < NQ_GROW; q += 256) {
        float4 a = m4[q];        // m[4q .. 4q+3]
        float4 b = m4[q + 1];    // m[4q+4 .. 4q+7]
        float4 v = make_float4(apv.x * a.w, apv.y * b.x, apv.z * b.y, apv.w * b.z);
        *reinterpret_cast<float4*>(dst + 3 + 4 * q) = v;
    }
    if (tid == 0) {
        dst[0] = __ldg(ap + 0) * g_m[0];
        dst[1] = __ldg(ap + 1) * g_m[1];
        dst[2] = __ldg(ap + 2) * g_m[2];
    } else if (tid == 1) {
        dst[WD - 1] = __ldg(ap + 7) * g_m[WD - 1];
    }
}

// ---------------------------------------------------------------------------
extern "C" void kernel_launch(void* const* d_in, const int* in_sizes, int n_in,
                              void* d_out, int out_size) {
    const float* x    = (const float*)d_in[0];
    const float* W    = (const float*)d_in[1];
    const float* ow   = (const float*)d_in[2];
    const float* st   = (const float*)d_in[3];
    const float* sa   = (const float*)d_in[4];
    const float* sgr  = (const float*)d_in[5];
    const float* og   = (const float*)d_in[6];
    const int*   tim  = (const int*)d_in[7];
    float* out = (float*)d_out;

    k_fusedW<<<dim3(KBLK, NSPLIT), 256>>>(W, st, sgr);
    k_finalize<<<WD / 256, 256>>>(out, x, ow, sa, og, tim);
    k_saog<<<(NQ_SAOG + 255) / 256, 256>>>(out, sa, og, ow, tim);
    k_grad<<<WIDTH, 256>>>(out);
}